// round 12
// baseline (speedup 1.0000x reference)
#include <cuda_runtime.h>
#include <cstdint>

#define N_DIM   512
#define K_DIM   32768
#define L_DIM   64
#define KTILE   128
#define TOUT    1048608
#define FR_PITCH 66

#define WPITCH  40                       // floats per staged row (bank = 8*qid+grp)
#define STG_FL  (8 * WPITCH)             // 320 floats per stage
#define DEPTH   6
#define WARP_FL (DEPTH * STG_FL)         // 1920 floats per warp ring
#define SM_FL   8448                     // max(4*1920=7680, 128*66=8448)

// V pre-formatted as tf32 B-fragments: [ss(64)][bt(8)][lane(32)] float2
__device__ float2 g_vf[64 * 8 * 32];

static __device__ __forceinline__ uint32_t f2tf32(float f) {
    uint32_t u;
    asm("cvt.rna.tf32.f32 %0, %1;" : "=r"(u) : "f"(f));
    return u;
}
static __device__ __forceinline__ uint32_t smem_u32(const void* p) {
    uint32_t a;
    asm("{ .reg .u64 t; cvta.to.shared.u64 t, %1; cvt.u32.u64 %0, t; }" : "=r"(a) : "l"(p));
    return a;
}
static __device__ __forceinline__ void cp_async16(uint32_t dst, const void* src) {
    asm volatile("cp.async.cg.shared.global [%0], [%1], 16;" :: "r"(dst), "l"(src));
}
static __device__ __forceinline__ void cp_commit() {
    asm volatile("cp.async.commit_group;" ::: "memory");
}
template <int N> static __device__ __forceinline__ void cp_wait() {
    asm volatile("cp.async.wait_group %0;" :: "n"(N) : "memory");
}
static __device__ __forceinline__ void mma_tf32(float d[4], const uint32_t a[4],
                                                uint32_t b0, uint32_t b1) {
    asm volatile(
        "mma.sync.aligned.m16n8k8.row.col.f32.tf32.tf32.f32 "
        "{%0,%1,%2,%3}, {%4,%5,%6,%7}, {%8,%9}, {%0,%1,%2,%3};"
        : "+f"(d[0]), "+f"(d[1]), "+f"(d[2]), "+f"(d[3])
        : "r"(a[0]), "r"(a[1]), "r"(a[2]), "r"(a[3]), "r"(b0), "r"(b1));
}

// ---- fused prep: V -> tf32 B-fragments (RNA), zero boundary tiles ----
__global__ void prep_kernel(const float* __restrict__ V, float* __restrict__ y) {
    const int idx = blockIdx.x * blockDim.x + threadIdx.x;
    if (idx < 16384) {
        const int lane = idx & 31;
        const int bt   = (idx >> 5) & 7;
        const int ss   = idx >> 8;
        const int grp  = lane >> 2, qid = lane & 3;
        const int l = bt * 8 + grp;
        const int n = ss * 8 + qid;
        float2 v;
        v.x = __uint_as_float(f2tf32(V[l * N_DIM + n]));
        v.y = __uint_as_float(f2tf32(V[l * N_DIM + n + 4]));
        g_vf[idx] = v;
    } else {
        const int i = idx - 16384;
        if (i < 8 * 257 * 32) {
            const int b = i / (257 * 32);
            const int r = i % (257 * 32);
            const int t = r >> 5, j = r & 31;
            y[(size_t)b * TOUT + (size_t)t * 4096 + j] = 0.f;
        }
    }
}

// ---- main: CTA = (b, 128 frames), 4 free-running warps, per-warp cp.async ring,
//      cross-iteration B double-buffer hoisted ABOVE the ring wait ----
__global__ void __launch_bounds__(128, 4)
decoder_kernel(const float* __restrict__ c, float* __restrict__ y) {
    __shared__ __align__(16) float sm[SM_FL];

    const int tid  = threadIdx.x;
    const int wid  = tid >> 5;
    const int lane = tid & 31;
    const int grp  = lane >> 2;
    const int qid  = lane & 3;
    const int k0   = blockIdx.x * KTILE;
    const int b    = blockIdx.y;
    const int wm   = wid * 32;

    const float* cw = c + ((size_t)b * N_DIM) * K_DIM + (size_t)(k0 + wm);
    float* ring = sm + wid * WARP_FL;
    const uint32_t ring_a = smem_u32(ring);

    const int r0  = lane >> 3;          // 0..3
    const int seg = lane & 7;           // 0..7

    float acc[2][8][4];
    #pragma unroll
    for (int mt = 0; mt < 2; ++mt)
        #pragma unroll
        for (int bt = 0; bt < 8; ++bt)
            #pragma unroll
            for (int r = 0; r < 4; ++r) acc[mt][bt][r] = 0.f;

    // prologue: A stages 0..4
    #pragma unroll
    for (int ps = 0; ps < DEPTH - 1; ++ps) {
        const uint32_t dst = ring_a + (uint32_t)(ps * STG_FL * 4);
        #pragma unroll
        for (int j = 0; j < 2; ++j) {
            const int row = r0 + 4 * j;
            cp_async16(dst + (uint32_t)((row * WPITCH + seg * 4) * 4),
                       cw + (size_t)(8 * ps + row) * K_DIM + seg * 4);
        }
        cp_commit();
    }

    // prologue: B fragments for ss = 0
    uint32_t bfc[8][2];
    {
        const float2* vf0 = g_vf + lane;
        #pragma unroll
        for (int bt = 0; bt < 8; ++bt) {
            float2 bv = __ldg(vf0 + bt * 32);
            bfc[bt][0] = __float_as_uint(bv.x);
            bfc[bt][1] = __float_as_uint(bv.y);
        }
    }

    int slot  = 0;              // = ss % DEPTH
    int tslot = DEPTH - 1;      // = (ss + DEPTH - 1) % DEPTH

    #pragma unroll 4
    for (int ss = 0; ss < 64; ++ss) {
        // issue A stage ss+5 into the slot consumed at ss-1
        if (ss + DEPTH - 1 < 64) {
            const int ts = ss + DEPTH - 1;
            const uint32_t dst = ring_a + (uint32_t)(tslot * STG_FL * 4);
            #pragma unroll
            for (int j = 0; j < 2; ++j) {
                const int row = r0 + 4 * j;
                cp_async16(dst + (uint32_t)((row * WPITCH + seg * 4) * 4),
                           cw + (size_t)(8 * ts + row) * K_DIM + seg * 4);
            }
        }
        cp_commit();                    // always commit (empty groups at tail)

        // prefetch NEXT iteration's B fragments BEFORE the ring wait:
        // any L1-miss latency overlaps cp.async wait + this iteration's MMAs
        uint32_t bfn[8][2];
        {
            const int ssn = (ss + 1 < 64) ? ss + 1 : 63;
            const float2* vf = g_vf + ssn * 256 + lane;
            #pragma unroll
            for (int bt = 0; bt < 8; ++bt) {
                float2 bv = __ldg(vf + bt * 32);
                bfn[bt][0] = __float_as_uint(bv.x);
                bfn[bt][1] = __float_as_uint(bv.y);
            }
        }

        cp_wait<DEPTH - 2>();           // A stage ss resident
        __syncwarp();

        // A fragments: raw fp32 bits straight from SMEM (HW uses high 19 bits)
        const float* cs = ring + slot * STG_FL;
        const uint32_t* ar0 = reinterpret_cast<const uint32_t*>(cs + qid * WPITCH + grp);
        const uint32_t* ar1 = reinterpret_cast<const uint32_t*>(cs + (qid + 4) * WPITCH + grp);
        uint32_t a[2][4];
        #pragma unroll
        for (int mt = 0; mt < 2; ++mt) {
            a[mt][0] = ar0[16 * mt];
            a[mt][1] = ar0[16 * mt + 8];
            a[mt][2] = ar1[16 * mt];
            a[mt][3] = ar1[16 * mt + 8];
        }

        #pragma unroll
        for (int bt = 0; bt < 8; ++bt) {
            mma_tf32(acc[0][bt], a[0], bfc[bt][0], bfc[bt][1]);
            mma_tf32(acc[1][bt], a[1], bfc[bt][0], bfc[bt][1]);
        }

        // rotate B buffers (renamed under unroll)
        #pragma unroll
        for (int bt = 0; bt < 8; ++bt) {
            bfc[bt][0] = bfn[bt][0];
            bfc[bt][1] = bfn[bt][1];
        }

        if (++slot == DEPTH) slot = 0;
        if (++tslot == DEPTH) tslot = 0;
    }

    __syncthreads();   // rings dead; reuse sm as frame buffer

    // ---- epilogue: stage frames, overlap-add ----
    float* fr = sm;
    #pragma unroll
    for (int mt = 0; mt < 2; ++mt) {
        #pragma unroll
        for (int bt = 0; bt < 8; ++bt) {
            const int row = wm + mt * 16 + grp;
            const int col = bt * 8 + 2 * qid;
            *reinterpret_cast<float2*>(fr + row * FR_PITCH + col) =
                make_float2(acc[mt][bt][0], acc[mt][bt][1]);
            *reinterpret_cast<float2*>(fr + (row + 8) * FR_PITCH + col) =
                make_float2(acc[mt][bt][2], acc[mt][bt][3]);
        }
    }
    __syncthreads();

    float* yb = y + (size_t)b * TOUT;
    const int k = tid;
    if (k == 0) {
        #pragma unroll
        for (int j = 0; j < 32; ++j)
            atomicAdd(&yb[(size_t)32 * k0 + j], fr[j]);
    } else {
        const float* f0 = fr + k * FR_PITCH;
        const float* f1 = fr + (k - 1) * FR_PITCH + 32;
        float4* o = reinterpret_cast<float4*>(yb + (size_t)32 * (k0 + k));
        #pragma unroll
        for (int q = 0; q < 8; ++q)
            o[q] = make_float4(f0[4*q+0] + f1[4*q+0], f0[4*q+1] + f1[4*q+1],
                               f0[4*q+2] + f1[4*q+2], f0[4*q+3] + f1[4*q+3]);
    }
    if (k == 127) {
        const float* f1 = fr + 127 * FR_PITCH + 32;
        #pragma unroll
        for (int j = 0; j < 32; ++j)
            atomicAdd(&yb[(size_t)32 * (k0 + KTILE) + j], f1[j]);
    }
}

extern "C" void kernel_launch(void* const* d_in, const int* in_sizes, int n_in,
                              void* d_out, int out_size) {
    const float* c = (const float*)d_in[0];
    const float* V = (const float*)d_in[1];
    if (in_sizes[0] == L_DIM * N_DIM) { c = (const float*)d_in[1]; V = (const float*)d_in[0]; }
    float* y = (float*)d_out;

    const int prep_threads = 16384 + 8 * 257 * 32;
    prep_kernel<<<(prep_threads + 255) / 256, 256>>>(V, y);

    dim3 grid(K_DIM / KTILE, 8);
    decoder_kernel<<<grid, 128>>>(c, y);
}

// round 13
// speedup vs baseline: 1.1578x; 1.1578x over previous
#include <cuda_runtime.h>
#include <cstdint>

#define N_DIM   512
#define K_DIM   32768
#define L_DIM   64
#define KTILE   128
#define TOUT    1048608
#define FR_PITCH 66

#define WPITCH  40                       // floats per staged row (bank = 8*qid+grp)
#define STG_FL  (8 * WPITCH)             // 320 floats per stage
#define DEPTH   6
#define WARP_FL (DEPTH * STG_FL)         // 1920 floats per warp ring
#define SM_FL   8448                     // max(4*1920=7680, 128*66=8448)

// V pre-formatted as tf32 B-fragments: [ss(64)][bt(8)][lane(32)] float2
__device__ float2 g_vf[64 * 8 * 32];

static __device__ __forceinline__ uint32_t f2tf32(float f) {
    uint32_t u;
    asm("cvt.rna.tf32.f32 %0, %1;" : "=r"(u) : "f"(f));
    return u;
}
static __device__ __forceinline__ uint32_t smem_u32(const void* p) {
    uint32_t a;
    asm("{ .reg .u64 t; cvta.to.shared.u64 t, %1; cvt.u32.u64 %0, t; }" : "=r"(a) : "l"(p));
    return a;
}
static __device__ __forceinline__ void cp_async16(uint32_t dst, const void* src) {
    asm volatile("cp.async.cg.shared.global [%0], [%1], 16;" :: "r"(dst), "l"(src));
}
static __device__ __forceinline__ void cp_commit() {
    asm volatile("cp.async.commit_group;" ::: "memory");
}
template <int N> static __device__ __forceinline__ void cp_wait() {
    asm volatile("cp.async.wait_group %0;" :: "n"(N) : "memory");
}
static __device__ __forceinline__ void mma_tf32(float d[4], const uint32_t a[4],
                                                uint32_t b0, uint32_t b1) {
    asm volatile(
        "mma.sync.aligned.m16n8k8.row.col.f32.tf32.tf32.f32 "
        "{%0,%1,%2,%3}, {%4,%5,%6,%7}, {%8,%9}, {%0,%1,%2,%3};"
        : "+f"(d[0]), "+f"(d[1]), "+f"(d[2]), "+f"(d[3])
        : "r"(a[0]), "r"(a[1]), "r"(a[2]), "r"(a[3]), "r"(b0), "r"(b1));
}

// ---- fused prep: V -> tf32 B-fragments (RNA), zero boundary tiles ----
__global__ void prep_kernel(const float* __restrict__ V, float* __restrict__ y) {
    const int idx = blockIdx.x * blockDim.x + threadIdx.x;
    if (idx < 16384) {
        const int lane = idx & 31;
        const int bt   = (idx >> 5) & 7;
        const int ss   = idx >> 8;
        const int grp  = lane >> 2, qid = lane & 3;
        const int l = bt * 8 + grp;
        const int n = ss * 8 + qid;
        float2 v;
        v.x = __uint_as_float(f2tf32(V[l * N_DIM + n]));
        v.y = __uint_as_float(f2tf32(V[l * N_DIM + n + 4]));
        g_vf[idx] = v;
    } else {
        const int i = idx - 16384;
        if (i < 8 * 257 * 32) {
            const int b = i / (257 * 32);
            const int r = i % (257 * 32);
            const int t = r >> 5, j = r & 31;
            y[(size_t)b * TOUT + (size_t)t * 4096 + j] = 0.f;
        }
    }
}

// ---- main: CTA = (b, 128 frames), 4 free-running warps, per-warp cp.async ring,
//      cross-iteration B double-buffer, B prefetch issued before the ring wait ----
__global__ void __launch_bounds__(128, 4)
decoder_kernel(const float* __restrict__ c, float* __restrict__ y) {
    __shared__ __align__(16) float sm[SM_FL];

    const int tid  = threadIdx.x;
    const int wid  = tid >> 5;
    const int lane = tid & 31;
    const int grp  = lane >> 2;
    const int qid  = lane & 3;
    const int k0   = blockIdx.x * KTILE;
    const int b    = blockIdx.y;
    const int wm   = wid * 32;

    const float* cw = c + ((size_t)b * N_DIM) * K_DIM + (size_t)(k0 + wm);
    float* ring = sm + wid * WARP_FL;
    const uint32_t ring_a = smem_u32(ring);

    const int r0  = lane >> 3;          // 0..3
    const int seg = lane & 7;           // 0..7

    float acc[2][8][4];
    #pragma unroll
    for (int mt = 0; mt < 2; ++mt)
        #pragma unroll
        for (int bt = 0; bt < 8; ++bt)
            #pragma unroll
            for (int r = 0; r < 4; ++r) acc[mt][bt][r] = 0.f;

    // prologue: A stages 0..4
    #pragma unroll
    for (int ps = 0; ps < DEPTH - 1; ++ps) {
        const uint32_t dst = ring_a + (uint32_t)(ps * STG_FL * 4);
        #pragma unroll
        for (int j = 0; j < 2; ++j) {
            const int row = r0 + 4 * j;
            cp_async16(dst + (uint32_t)((row * WPITCH + seg * 4) * 4),
                       cw + (size_t)(8 * ps + row) * K_DIM + seg * 4);
        }
        cp_commit();
    }

    // prologue: B fragments for ss = 0
    uint32_t bfc[8][2];
    {
        const float2* vf0 = g_vf + lane;
        #pragma unroll
        for (int bt = 0; bt < 8; ++bt) {
            float2 bv = __ldg(vf0 + bt * 32);
            bfc[bt][0] = __float_as_uint(bv.x);
            bfc[bt][1] = __float_as_uint(bv.y);
        }
    }

    int slot  = 0;              // = ss % DEPTH
    int tslot = DEPTH - 1;      // = (ss + DEPTH - 1) % DEPTH

    #pragma unroll 2
    for (int ss = 0; ss < 64; ++ss) {
        // issue A stage ss+5 into the slot consumed at ss-1
        if (ss + DEPTH - 1 < 64) {
            const int ts = ss + DEPTH - 1;
            const uint32_t dst = ring_a + (uint32_t)(tslot * STG_FL * 4);
            #pragma unroll
            for (int j = 0; j < 2; ++j) {
                const int row = r0 + 4 * j;
                cp_async16(dst + (uint32_t)((row * WPITCH + seg * 4) * 4),
                           cw + (size_t)(8 * ts + row) * K_DIM + seg * 4);
            }
        }
        cp_commit();                    // always commit (empty groups at tail)

        // prefetch NEXT iteration's B fragments BEFORE the ring wait:
        // B L1-miss latency overlaps the cp.async wait AND this iter's MMAs
        uint32_t bfn[8][2];
        {
            const int ssn = (ss + 1 < 64) ? ss + 1 : 63;
            const float2* vf = g_vf + ssn * 256 + lane;
            #pragma unroll
            for (int bt = 0; bt < 8; ++bt) {
                float2 bv = __ldg(vf + bt * 32);
                bfn[bt][0] = __float_as_uint(bv.x);
                bfn[bt][1] = __float_as_uint(bv.y);
            }
        }

        cp_wait<DEPTH - 2>();           // A stage ss resident
        __syncwarp();

        // A fragments: raw fp32 bits straight from SMEM (HW uses high 19 bits)
        const float* cs = ring + slot * STG_FL;
        const uint32_t* ar0 = reinterpret_cast<const uint32_t*>(cs + qid * WPITCH + grp);
        const uint32_t* ar1 = reinterpret_cast<const uint32_t*>(cs + (qid + 4) * WPITCH + grp);
        uint32_t a[2][4];
        #pragma unroll
        for (int mt = 0; mt < 2; ++mt) {
            a[mt][0] = ar0[16 * mt];
            a[mt][1] = ar0[16 * mt + 8];
            a[mt][2] = ar1[16 * mt];
            a[mt][3] = ar1[16 * mt + 8];
        }

        #pragma unroll
        for (int bt = 0; bt < 8; ++bt) {
            mma_tf32(acc[0][bt], a[0], bfc[bt][0], bfc[bt][1]);
            mma_tf32(acc[1][bt], a[1], bfc[bt][0], bfc[bt][1]);
        }

        // rotate B buffers (renamed away under unroll 2)
        #pragma unroll
        for (int bt = 0; bt < 8; ++bt) {
            bfc[bt][0] = bfn[bt][0];
            bfc[bt][1] = bfn[bt][1];
        }

        if (++slot == DEPTH) slot = 0;
        if (++tslot == DEPTH) tslot = 0;
    }

    __syncthreads();   // rings dead; reuse sm as frame buffer

    // ---- epilogue: stage frames, overlap-add ----
    float* fr = sm;
    #pragma unroll
    for (int mt = 0; mt < 2; ++mt) {
        #pragma unroll
        for (int bt = 0; bt < 8; ++bt) {
            const int row = wm + mt * 16 + grp;
            const int col = bt * 8 + 2 * qid;
            *reinterpret_cast<float2*>(fr + row * FR_PITCH + col) =
                make_float2(acc[mt][bt][0], acc[mt][bt][1]);
            *reinterpret_cast<float2*>(fr + (row + 8) * FR_PITCH + col) =
                make_float2(acc[mt][bt][2], acc[mt][bt][3]);
        }
    }
    __syncthreads();

    float* yb = y + (size_t)b * TOUT;
    const int k = tid;
    if (k == 0) {
        #pragma unroll
        for (int j = 0; j < 32; ++j)
            atomicAdd(&yb[(size_t)32 * k0 + j], fr[j]);
    } else {
        const float* f0 = fr + k * FR_PITCH;
        const float* f1 = fr + (k - 1) * FR_PITCH + 32;
        float4* o = reinterpret_cast<float4*>(yb + (size_t)32 * (k0 + k));
        #pragma unroll
        for (int q = 0; q < 8; ++q)
            o[q] = make_float4(f0[4*q+0] + f1[4*q+0], f0[4*q+1] + f1[4*q+1],
                               f0[4*q+2] + f1[4*q+2], f0[4*q+3] + f1[4*q+3]);
    }
    if (k == 127) {
        const float* f1 = fr + 127 * FR_PITCH + 32;
        #pragma unroll
        for (int j = 0; j < 32; ++j)
            atomicAdd(&yb[(size_t)32 * (k0 + KTILE) + j], f1[j]);
    }
}

extern "C" void kernel_launch(void* const* d_in, const int* in_sizes, int n_in,
                              void* d_out, int out_size) {
    const float* c = (const float*)d_in[0];
    const float* V = (const float*)d_in[1];
    if (in_sizes[0] == L_DIM * N_DIM) { c = (const float*)d_in[1]; V = (const float*)d_in[0]; }
    float* y = (float*)d_out;

    const int prep_threads = 16384 + 8 * 257 * 32;
    prep_kernel<<<(prep_threads + 255) / 256, 256>>>(V, y);

    dim3 grid(K_DIM / KTILE, 8);
    decoder_kernel<<<grid, 128>>>(c, y);
}

// round 16
// speedup vs baseline: 1.1584x; 1.0005x over previous
#include <cuda_runtime.h>
#include <cstdint>

#define N_DIM   512
#define K_DIM   32768
#define L_DIM   64
#define KTILE   128
#define TOUT    1048608
#define FR_PITCH 66

#define WPITCH  40                       // floats per staged row (bank = 8*qid+grp)
#define STG_FL  (8 * WPITCH)             // 320 floats per stage
#define DEPTH   4
#define WARP_FL (DEPTH * STG_FL)         // 1280 floats per warp ring
#define SM_FL   5120                     // ring 4*1280; epilogue 65*66=4290 fits
                                         // 20.5 KB/CTA -> L1D ~146 KB: g_vf resident

// V pre-formatted as tf32 B-fragments: [ss(64)][bt(8)][lane(32)] float2 (128 KB)
__device__ float2 g_vf[64 * 8 * 32];

static __device__ __forceinline__ uint32_t f2tf32(float f) {
    uint32_t u;
    asm("cvt.rna.tf32.f32 %0, %1;" : "=r"(u) : "f"(f));
    return u;
}
static __device__ __forceinline__ uint32_t smem_u32(const void* p) {
    uint32_t a;
    asm("{ .reg .u64 t; cvta.to.shared.u64 t, %1; cvt.u32.u64 %0, t; }" : "=r"(a) : "l"(p));
    return a;
}
static __device__ __forceinline__ void cp_async16(uint32_t dst, const void* src) {
    asm volatile("cp.async.cg.shared.global [%0], [%1], 16;" :: "r"(dst), "l"(src));
}
static __device__ __forceinline__ void cp_commit() {
    asm volatile("cp.async.commit_group;" ::: "memory");
}
template <int N> static __device__ __forceinline__ void cp_wait() {
    asm volatile("cp.async.wait_group %0;" :: "n"(N) : "memory");
}
static __device__ __forceinline__ void mma_tf32(float d[4], const uint32_t a[4],
                                                uint32_t b0, uint32_t b1) {
    asm volatile(
        "mma.sync.aligned.m16n8k8.row.col.f32.tf32.tf32.f32 "
        "{%0,%1,%2,%3}, {%4,%5,%6,%7}, {%8,%9}, {%0,%1,%2,%3};"
        : "+f"(d[0]), "+f"(d[1]), "+f"(d[2]), "+f"(d[3])
        : "r"(a[0]), "r"(a[1]), "r"(a[2]), "r"(a[3]), "r"(b0), "r"(b1));
}

// ---- fused prep: V -> tf32 B-fragments (RNA), zero boundary tiles ----
__global__ void prep_kernel(const float* __restrict__ V, float* __restrict__ y) {
    const int idx = blockIdx.x * blockDim.x + threadIdx.x;
    if (idx < 16384) {
        const int lane = idx & 31;
        const int bt   = (idx >> 5) & 7;
        const int ss   = idx >> 8;
        const int grp  = lane >> 2, qid = lane & 3;
        const int l = bt * 8 + grp;
        const int n = ss * 8 + qid;
        float2 v;
        v.x = __uint_as_float(f2tf32(V[l * N_DIM + n]));
        v.y = __uint_as_float(f2tf32(V[l * N_DIM + n + 4]));
        g_vf[idx] = v;
    } else {
        const int i = idx - 16384;
        if (i < 8 * 257 * 32) {
            const int b = i / (257 * 32);
            const int r = i % (257 * 32);
            const int t = r >> 5, j = r & 31;
            y[(size_t)b * TOUT + (size_t)t * 4096 + j] = 0.f;
        }
    }
}

// ---- main: CTA = (b, 128 frames), 4 free-running warps, per-warp cp.async ring,
//      cross-iteration B double-buffer; small SMEM so g_vf is L1-resident ----
__global__ void __launch_bounds__(128, 4)
decoder_kernel(const float* __restrict__ c, float* __restrict__ y) {
    __shared__ __align__(16) float sm[SM_FL];

    const int tid  = threadIdx.x;
    const int wid  = tid >> 5;
    const int lane = tid & 31;
    const int grp  = lane >> 2;
    const int qid  = lane & 3;
    const int k0   = blockIdx.x * KTILE;
    const int b    = blockIdx.y;
    const int wm   = wid * 32;

    const float* cw = c + ((size_t)b * N_DIM) * K_DIM + (size_t)(k0 + wm);
    float* ring = sm + wid * WARP_FL;
    const uint32_t ring_a = smem_u32(ring);

    const int r0  = lane >> 3;          // 0..3
    const int seg = lane & 7;           // 0..7

    float acc[2][8][4];
    #pragma unroll
    for (int mt = 0; mt < 2; ++mt)
        #pragma unroll
        for (int bt = 0; bt < 8; ++bt)
            #pragma unroll
            for (int r = 0; r < 4; ++r) acc[mt][bt][r] = 0.f;

    // prologue: A stages 0..2
    #pragma unroll
    for (int ps = 0; ps < DEPTH - 1; ++ps) {
        const uint32_t dst = ring_a + (uint32_t)(ps * STG_FL * 4);
        #pragma unroll
        for (int j = 0; j < 2; ++j) {
            const int row = r0 + 4 * j;
            cp_async16(dst + (uint32_t)((row * WPITCH + seg * 4) * 4),
                       cw + (size_t)(8 * ps + row) * K_DIM + seg * 4);
        }
        cp_commit();
    }

    // prologue: B fragments for ss = 0
    uint32_t bfc[8][2];
    {
        const float2* vf0 = g_vf + lane;
        #pragma unroll
        for (int bt = 0; bt < 8; ++bt) {
            float2 bv = __ldg(vf0 + bt * 32);
            bfc[bt][0] = __float_as_uint(bv.x);
            bfc[bt][1] = __float_as_uint(bv.y);
        }
    }

    int slot  = 0;              // = ss % DEPTH
    int tslot = DEPTH - 1;      // = (ss + DEPTH - 1) % DEPTH

    #pragma unroll 2
    for (int ss = 0; ss < 64; ++ss) {
        // issue A stage ss+3 into the slot consumed at ss-1
        if (ss + DEPTH - 1 < 64) {
            const int ts = ss + DEPTH - 1;
            const uint32_t dst = ring_a + (uint32_t)(tslot * STG_FL * 4);
            #pragma unroll
            for (int j = 0; j < 2; ++j) {
                const int row = r0 + 4 * j;
                cp_async16(dst + (uint32_t)((row * WPITCH + seg * 4) * 4),
                           cw + (size_t)(8 * ts + row) * K_DIM + seg * 4);
            }
        }
        cp_commit();                    // always commit (empty groups at tail)

        // prefetch NEXT iteration's B fragments before the ring wait
        uint32_t bfn[8][2];
        {
            const int ssn = (ss + 1 < 64) ? ss + 1 : 63;
            const float2* vf = g_vf + ssn * 256 + lane;
            #pragma unroll
            for (int bt = 0; bt < 8; ++bt) {
                float2 bv = __ldg(vf + bt * 32);
                bfn[bt][0] = __float_as_uint(bv.x);
                bfn[bt][1] = __float_as_uint(bv.y);
            }
        }

        cp_wait<DEPTH - 2>();           // A stage ss resident
        __syncwarp();

        // A fragments: raw fp32 bits straight from SMEM (HW uses high 19 bits)
        const float* cs = ring + slot * STG_FL;
        const uint32_t* ar0 = reinterpret_cast<const uint32_t*>(cs + qid * WPITCH + grp);
        const uint32_t* ar1 = reinterpret_cast<const uint32_t*>(cs + (qid + 4) * WPITCH + grp);
        uint32_t a[2][4];
        #pragma unroll
        for (int mt = 0; mt < 2; ++mt) {
            a[mt][0] = ar0[16 * mt];
            a[mt][1] = ar0[16 * mt + 8];
            a[mt][2] = ar1[16 * mt];
            a[mt][3] = ar1[16 * mt + 8];
        }

        #pragma unroll
        for (int bt = 0; bt < 8; ++bt) {
            mma_tf32(acc[0][bt], a[0], bfc[bt][0], bfc[bt][1]);
            mma_tf32(acc[1][bt], a[1], bfc[bt][0], bfc[bt][1]);
        }

        // rotate B buffers (renamed away under unroll 2)
        #pragma unroll
        for (int bt = 0; bt < 8; ++bt) {
            bfc[bt][0] = bfn[bt][0];
            bfc[bt][1] = bfn[bt][1];
        }

        if (++slot == DEPTH) slot = 0;
        if (++tslot == DEPTH) tslot = 0;
    }

    __syncthreads();   // rings dead; reuse sm as 65-row frame buffer

    // ---- epilogue, two passes over 65 staged rows ----
    float* fr = sm;
    float* yb = y + (size_t)b * TOUT;

    // pass 0: warps 0,1 stage frames 0..63 (frame 63 duplicated into row 64)
    if (wid < 2) {
        #pragma unroll
        for (int mt = 0; mt < 2; ++mt) {
            #pragma unroll
            for (int bt = 0; bt < 8; ++bt) {
                const int row = wm + mt * 16 + grp;
                const int col = bt * 8 + 2 * qid;
                *reinterpret_cast<float2*>(fr + row * FR_PITCH + col) =
                    make_float2(acc[mt][bt][0], acc[mt][bt][1]);
                *reinterpret_cast<float2*>(fr + (row + 8) * FR_PITCH + col) =
                    make_float2(acc[mt][bt][2], acc[mt][bt][3]);
                if (wid == 1 && mt == 1 && grp == 7)   // frame 63 -> row 64
                    *reinterpret_cast<float2*>(fr + 64 * FR_PITCH + col) =
                        make_float2(acc[mt][bt][2], acc[mt][bt][3]);
            }
        }
    }
    __syncthreads();

    if (tid < 64) {
        const int k = tid;
        if (k == 0) {
            #pragma unroll
            for (int j = 0; j < 32; ++j)
                atomicAdd(&yb[(size_t)32 * k0 + j], fr[j]);
        } else {
            const float* f0 = fr + k * FR_PITCH;
            const float* f1 = fr + (k - 1) * FR_PITCH + 32;
            float4* o = reinterpret_cast<float4*>(yb + (size_t)32 * (k0 + k));
            #pragma unroll
            for (int q = 0; q < 8; ++q)
                o[q] = make_float4(f0[4*q+0] + f1[4*q+0], f0[4*q+1] + f1[4*q+1],
                                   f0[4*q+2] + f1[4*q+2], f0[4*q+3] + f1[4*q+3]);
        }
    }
    __syncthreads();

    // pass 1: warps 2,3 stage frames 64..127 into rows 0..63 (row 64 = frame 63 kept)
    if (wid >= 2) {
        #pragma unroll
        for (int mt = 0; mt < 2; ++mt) {
            #pragma unroll
            for (int bt = 0; bt < 8; ++bt) {
                const int row = (wm - 64) + mt * 16 + grp;
                const int col = bt * 8 + 2 * qid;
                *reinterpret_cast<float2*>(fr + row * FR_PITCH + col) =
                    make_float2(acc[mt][bt][0], acc[mt][bt][1]);
                *reinterpret_cast<float2*>(fr + (row + 8) * FR_PITCH + col) =
                    make_float2(acc[mt][bt][2], acc[mt][bt][3]);
            }
        }
    }
    __syncthreads();

    if (tid >= 64) {
        const int k = tid;                 // global frame k (64..127)
        const float* f0 = fr + (k - 64) * FR_PITCH;
        const float* f1 = (k == 64) ? (fr + 64 * FR_PITCH + 32)
                                    : (fr + (k - 65) * FR_PITCH + 32);
        float4* o = reinterpret_cast<float4*>(yb + (size_t)32 * (k0 + k));
        #pragma unroll
        for (int q = 0; q < 8; ++q)
            o[q] = make_float4(f0[4*q+0] + f1[4*q+0], f0[4*q+1] + f1[4*q+1],
                               f0[4*q+2] + f1[4*q+2], f0[4*q+3] + f1[4*q+3]);
        if (k == 127) {
            const float* ft = fr + 63 * FR_PITCH + 32;
            #pragma unroll
            for (int j = 0; j < 32; ++j)
                atomicAdd(&yb[(size_t)32 * (k0 + KTILE) + j], ft[j]);
        }
    }
}

extern "C" void kernel_launch(void* const* d_in, const int* in_sizes, int n_in,
                              void* d_out, int out_size) {
    const float* c = (const float*)d_in[0];
    const float* V = (const float*)d_in[1];
    if (in_sizes[0] == L_DIM * N_DIM) { c = (const float*)d_in[1]; V = (const float*)d_in[0]; }
    float* y = (float*)d_out;

    const int prep_threads = 16384 + 8 * 257 * 32;
    prep_kernel<<<(prep_threads + 255) / 256, 256>>>(V, y);

    dim3 grid(K_DIM / KTILE, 8);
    decoder_kernel<<<grid, 128>>>(c, y);
}